// round 17
// baseline (speedup 1.0000x reference)
#include <cuda_runtime.h>
#include <cuda_fp16.h>
#include <stdint.h>

#define CB 2
#define CS 2048
#define CE 1024
#define CH 16
#define CDK 64
#define CM (CB * CS)   // 4096

// fp16 scratch (allocation-free, 16B-aligned)
__device__ __align__(16) __half g_q[CB * CH * CS * CDK];   // [b,h,s,d]
__device__ __align__(16) __half g_k[CB * CH * CS * CDK];
__device__ __align__(16) __half g_v[CB * CH * CS * CDK];
__device__ __align__(16) __half g_att[CB * CS * CE];       // [b,s,e]
__device__ __align__(16) __half g_aq[CM * CE];             // fp16 inputs
__device__ __align__(16) __half g_ak[CM * CE];
__device__ __align__(16) __half g_av[CM * CE];
__device__ __align__(16) __half g_wq[CE * CE];             // fp16 weights
__device__ __align__(16) __half g_wk[CE * CE];
__device__ __align__(16) __half g_wv[CE * CE];
__device__ __align__(16) __half g_wo[CE * CE];

// split-K attention partials (qt 8..15 split into 2 halves)
#define POHALF (8 * 32 * 128 * 64)     // fp32 out partials per half
#define PRSHALF (8 * 32 * 128)         // fp32 row-sum partials per half
__device__ __align__(16) float g_po[2][POHALF];
__device__ __align__(16) float g_prs[2][PRSHALF];

// ---------------------------------------------------------------------------
// PTX helpers
// ---------------------------------------------------------------------------
__device__ __forceinline__ uint32_t sptr(const void* p) {
    return (uint32_t)__cvta_generic_to_shared(p);
}
__device__ __forceinline__ void ldm_x4(uint32_t* r, uint32_t a) {
    asm volatile("ldmatrix.sync.aligned.m8n8.x4.shared.b16 {%0,%1,%2,%3}, [%4];\n"
                 : "=r"(r[0]), "=r"(r[1]), "=r"(r[2]), "=r"(r[3]) : "r"(a));
}
__device__ __forceinline__ void ldm_x4_t(uint32_t* r, uint32_t a) {
    asm volatile("ldmatrix.sync.aligned.m8n8.x4.trans.shared.b16 {%0,%1,%2,%3}, [%4];\n"
                 : "=r"(r[0]), "=r"(r[1]), "=r"(r[2]), "=r"(r[3]) : "r"(a));
}
__device__ __forceinline__ void mma16816(float* d, const uint32_t* a, const uint32_t* b) {
    asm volatile(
        "mma.sync.aligned.m16n8k16.row.col.f32.f16.f16.f32 "
        "{%0,%1,%2,%3},{%4,%5,%6,%7},{%8,%9},{%0,%1,%2,%3};\n"
        : "+f"(d[0]), "+f"(d[1]), "+f"(d[2]), "+f"(d[3])
        : "r"(a[0]), "r"(a[1]), "r"(a[2]), "r"(a[3]), "r"(b[0]), "r"(b[1]));
}
__device__ __forceinline__ void cpa16(uint32_t dst, const void* src) {
    asm volatile("cp.async.cg.shared.global [%0], [%1], 16;\n" :: "r"(dst), "l"(src));
}
__device__ __forceinline__ void cp_commit() {
    asm volatile("cp.async.commit_group;\n");
}
template <int N> __device__ __forceinline__ void cp_wait() {
    asm volatile("cp.async.wait_group %0;\n" :: "n"(N));
}
__device__ __forceinline__ uint32_t ex2h2(uint32_t x) {   // ex2 on packed half2
    uint32_t r;
    asm("ex2.approx.f16x2 %0, %1;" : "=r"(r) : "r"(x));
    return r;
}

// ---------------------------------------------------------------------------
// Fused fp32 -> fp16 conversions (blockIdx.y selects tensor)
// ---------------------------------------------------------------------------
__device__ __forceinline__ void cvt8(const float* in, __half* out, size_t i) {
    const float4* p = (const float4*)in + 2 * i;
    const float4 a = p[0], b = p[1];
    uint4 r; __half2 h;
    h = __floats2half2_rn(a.x, a.y); r.x = *(uint32_t*)&h;
    h = __floats2half2_rn(a.z, a.w); r.y = *(uint32_t*)&h;
    h = __floats2half2_rn(b.x, b.y); r.z = *(uint32_t*)&h;
    h = __floats2half2_rn(b.z, b.w); r.w = *(uint32_t*)&h;
    ((uint4*)out)[i] = r;
}

struct CvtArgs { const float* in[4]; __half* out[4]; };

__global__ void __launch_bounds__(256) cvt_multi(CvtArgs args, int n8) {
    const int i = blockIdx.x * 256 + threadIdx.x;
    if (i >= n8) return;
    cvt8(args.in[blockIdx.y], args.out[blockIdx.y], (size_t)i);
}

// ---------------------------------------------------------------------------
// Tensor-core GEMM: C (+)= A[M, klen] @ W[N, klen]^T (+ bias), fp16 operands.
// lda = row stride (full K). BM=BN=128, BK=64; 256 threads, warp tile 32x64,
// 3-stage cp.async pipeline. n_base shifts the N-block. ACC=1: fp32 RMW.
// ---------------------------------------------------------------------------
#define GK 72
#define GTILE (128 * GK)
#define GSTAGES 3
#define GEMM_SMEM (GSTAGES * 2 * GTILE * 2)   // 110592 bytes

template <int PERM, int ACC>
__device__ __forceinline__ void gemm_body(
    const __half* __restrict__ A, const __half* __restrict__ W,
    const float* __restrict__ bias, void* __restrict__ Cout,
    int lda, int klen, int N, int n_base, __half* As, __half* Ws)
{
    const int tid = threadIdx.x;
    const int wid = tid >> 5, lane = tid & 31;
    const int wm = wid & 3, wn = wid >> 2;
    const int m0 = blockIdx.y * 128;
    const int n0 = (blockIdx.x + n_base) * 128;

    float acc[2][8][4];
    #pragma unroll
    for (int i = 0; i < 2; i++)
        #pragma unroll
        for (int j = 0; j < 8; j++)
            #pragma unroll
            for (int q = 0; q < 4; q++) acc[i][j][q] = 0.f;

    auto load_stage = [&](int s, int k0) {
        #pragma unroll
        for (int i = 0; i < 4; i++) {
            const int idx = tid + i * 256, row = idx >> 3, c8 = idx & 7;
            cpa16(sptr(&As[s * GTILE + row * GK + c8 * 8]),
                  A + (size_t)(m0 + row) * lda + k0 + c8 * 8);
        }
        #pragma unroll
        for (int i = 0; i < 4; i++) {
            const int idx = tid + i * 256, row = idx >> 3, c8 = idx & 7;
            cpa16(sptr(&Ws[s * GTILE + row * GK + c8 * 8]),
                  W + (size_t)(n0 + row) * lda + k0 + c8 * 8);
        }
        cp_commit();
    };

    const int nk = klen / 64;
    load_stage(0, 0);
    load_stage(1, 64);

    int st = 0;
    for (int ks = 0; ks < nk; ks++) {
        if (ks + 2 < nk) cp_wait<1>(); else cp_wait<0>();
        __syncthreads();
        if (ks + 2 < nk) {
            int s2 = st + 2; if (s2 >= GSTAGES) s2 -= GSTAGES;
            load_stage(s2, (ks + 2) * 64);
        }

        const __half* as = As + st * GTILE;
        const __half* ws = Ws + st * GTILE;

        #pragma unroll
        for (int kk = 0; kk < 4; kk++) {
            uint32_t af[2][4];
            #pragma unroll
            for (int mi = 0; mi < 2; mi++) {
                const int row = wm * 32 + mi * 16 + (lane & 15);
                const int col = kk * 16 + (lane >> 4) * 8;
                ldm_x4(af[mi], sptr(&as[row * GK + col]));
            }
            uint32_t bf[4][4];
            #pragma unroll
            for (int nj = 0; nj < 4; nj++) {
                const int row = wn * 64 + nj * 16 + (lane & 7) + ((lane >> 4) << 3);
                const int col = kk * 16 + ((lane >> 3) & 1) * 8;
                ldm_x4(bf[nj], sptr(&ws[row * GK + col]));
            }
            #pragma unroll
            for (int mi = 0; mi < 2; mi++)
                #pragma unroll
                for (int ni = 0; ni < 8; ni++)
                    mma16816(acc[mi][ni], af[mi], &bf[ni >> 1][(ni & 1) * 2]);
        }
        if (++st >= GSTAGES) st = 0;
    }

    #pragma unroll
    for (int mi = 0; mi < 2; mi++) {
        #pragma unroll
        for (int ni = 0; ni < 8; ni++) {
            const int mr0 = m0 + wm * 32 + mi * 16 + (lane >> 2);
            const int col = n0 + wn * 64 + ni * 8 + (lane & 3) * 2;
            float v00 = acc[mi][ni][0], v01 = acc[mi][ni][1];
            float v10 = acc[mi][ni][2], v11 = acc[mi][ni][3];
            if (!ACC) {
                const float b0 = bias[col], b1 = bias[col + 1];
                v00 += b0; v01 += b1; v10 += b0; v11 += b1;
            }
            if (PERM) {
                __half* C = (__half*)Cout;
                const int h = col >> 6, d = col & 63;
                {
                    const int b = mr0 >> 11, s = mr0 & 2047;
                    __half2 hv = __floats2half2_rn(v00, v01);
                    *(__half2*)&C[(((size_t)(b * CH + h) * CS + s) * CDK) + d] = hv;
                }
                {
                    const int m1 = mr0 + 8;
                    const int b = m1 >> 11, s = m1 & 2047;
                    __half2 hv = __floats2half2_rn(v10, v11);
                    *(__half2*)&C[(((size_t)(b * CH + h) * CS + s) * CDK) + d] = hv;
                }
            } else {
                float* C = (float*)Cout;
                float* p0 = &C[(size_t)mr0 * N + col];
                float* p1 = &C[(size_t)(mr0 + 8) * N + col];
                if (ACC) {
                    float2 o0 = *(float2*)p0, o1 = *(float2*)p1;
                    v00 += o0.x; v01 += o0.y; v10 += o1.x; v11 += o1.y;
                }
                *(float2*)p0 = make_float2(v00, v01);
                *(float2*)p1 = make_float2(v10, v11);
            }
        }
    }
}

struct QKVArgs {
    const __half* A[3];
    const __half* W[3];
    const float* bias[3];
    __half* C[3];
    int n_base;
};

__global__ void __launch_bounds__(256, 2) qkv_gemm(QKVArgs args) {
    extern __shared__ __half gsm[];
    const int z = blockIdx.z;
    gemm_body<1, 0>(args.A[z], args.W[z], args.bias[z], args.C[z],
                    CE, CE, CE, args.n_base, gsm, gsm + GSTAGES * GTILE);
}

// Output projection K-quarters (K=256 each = one 4-head group).
__global__ void __launch_bounds__(256, 2) out_gemm_q0(
    const __half* __restrict__ A, const __half* __restrict__ W,
    const float* __restrict__ bias, float* __restrict__ C)
{
    extern __shared__ __half gsm[];
    gemm_body<0, 0>(A, W, bias, C, CE, CE / 4, CE, 0,
                    gsm, gsm + GSTAGES * GTILE);
}

__global__ void __launch_bounds__(256, 2) out_gemm_qacc(
    const __half* __restrict__ A, const __half* __restrict__ W,
    float* __restrict__ C)
{
    extern __shared__ __half gsm[];
    gemm_body<0, 1>(A, W, nullptr, C, CE, CE / 4, CE, 0,
                    gsm, gsm + GSTAGES * GTILE);
}

// ---------------------------------------------------------------------------
// Flash attention with SPLIT-K over long blocks, 4-head group (h_base).
//   grid (24, 8): y -> b = y>>2, h = h_base + (y&3).
// ---------------------------------------------------------------------------
#define ASTR 72

__global__ void __launch_bounds__(128, 3) attn_tc(
    const __half* __restrict__ Q, const __half* __restrict__ K,
    const __half* __restrict__ V, __half* __restrict__ O, int h_base)
{
    extern __shared__ __half sm[];
    __half* Qs = sm;
    __half* Ksb = sm + 128 * ASTR;
    __half* Vsb = Ksb + 2 * 64 * ASTR;

    const int bx = blockIdx.x;
    int qt, kt0, nloc, half;
    if (bx < 16) {
        qt = 15 - (bx >> 1); half = bx & 1;
        kt0 = half * (qt + 1); nloc = qt + 1;
    } else {
        qt = 23 - bx; half = -1;
        kt0 = 0; nloc = 2 * qt + 2;
    }

    const int b = blockIdx.y >> 2;
    const int h = h_base + (blockIdx.y & 3);
    const int bh = b * 16 + h;
    const int tid = threadIdx.x, wid = tid >> 5, lane = tid & 31;
    const size_t base = (size_t)bh * CS * CDK;

    const int krow = tid >> 3;
    const int kc = tid & 7;

    auto load_kv = [&](int s, int kt) {
        const __half* Kb = K + base + (size_t)(kt * 64) * CDK;
        const __half* Vb = V + base + (size_t)(kt * 64) * CDK;
        #pragma unroll
        for (int i = 0; i < 4; i++) {
            const int row = krow + i * 16;
            cpa16(sptr(&Ksb[s * 64 * ASTR + row * ASTR + kc * 8]),
                  Kb + row * CDK + kc * 8);
            cpa16(sptr(&Vsb[s * 64 * ASTR + row * ASTR + kc * 8]),
                  Vb + row * CDK + kc * 8);
        }
        cp_commit();
    };

    load_kv(0, kt0);

    #pragma unroll
    for (int i = 0; i < 8; i++) {
        const int idx = tid + i * 128, row = idx >> 3, c8 = idx & 7;
        *(uint4*)&Qs[row * ASTR + c8 * 8] =
            *(const uint4*)(Q + base + (size_t)(qt * 128 + row) * CDK + c8 * 8);
    }
    __syncthreads();

    uint32_t qf[4][2][4];
    #pragma unroll
    for (int kk = 0; kk < 4; kk++)
        #pragma unroll
        for (int mi = 0; mi < 2; mi++) {
            const int row = wid * 32 + mi * 16 + (lane & 15);
            const int col = kk * 16 + (lane >> 4) * 8;
            ldm_x4(qf[kk][mi], sptr(&Qs[row * ASTR + col]));
        }

    float out[2][8][4];
    float rs[2][4];
    #pragma unroll
    for (int mi = 0; mi < 2; mi++) {
        #pragma unroll
        for (int n = 0; n < 8; n++)
            #pragma unroll
            for (int q = 0; q < 4; q++) out[mi][n][q] = 0.f;
        #pragma unroll
        for (int q = 0; q < 4; q++) rs[mi][q] = 0.f;
    }

    const uint32_t ONE2 = 0x3C003C00u;
    uint32_t onesb[2] = {ONE2, ONE2};

    const float c2 = 0.180336880f;         // log2(e) / 8
    const int wrow0 = qt * 128 + wid * 32;

    for (int t = 0; t < nloc; t++) {
        cp_wait<0>();
        __syncthreads();
        if (t + 1 < nloc) load_kv((t + 1) & 1, kt0 + t + 1);

        const int kt = kt0 + t;
        const int ct = kt * 64;
        if (ct <= wrow0 + 31) {
            const __half* ks = Ksb + (t & 1) * 64 * ASTR;
            const __half* vs = Vsb + (t & 1) * 64 * ASTR;
            const bool need_mask = (ct + 63) > wrow0;

            #pragma unroll
            for (int nj = 0; nj < 4; nj++) {
                float sc[2][2][4];
                #pragma unroll
                for (int mi = 0; mi < 2; mi++)
                    #pragma unroll
                    for (int n = 0; n < 2; n++)
                        #pragma unroll
                        for (int q = 0; q < 4; q++) sc[mi][n][q] = 0.f;
                #pragma unroll
                for (int kk = 0; kk < 4; kk++) {
                    uint32_t kf[4];
                    const int row = nj * 16 + (lane & 7) + ((lane >> 4) << 3);
                    const int col = kk * 16 + ((lane >> 3) & 1) * 8;
                    ldm_x4(kf, sptr(&ks[row * ASTR + col]));
                    #pragma unroll
                    for (int mi = 0; mi < 2; mi++) {
                        mma16816(sc[mi][0], qf[kk][mi], &kf[0]);
                        mma16816(sc[mi][1], qf[kk][mi], &kf[2]);
                    }
                }

                uint32_t pf[2][4];
                #pragma unroll
                for (int mi = 0; mi < 2; mi++) {
                    const int rg0 = wrow0 + mi * 16 + (lane >> 2);
                    #pragma unroll
                    for (int n = 0; n < 2; n++) {
                        float t0 = fmaf(sc[mi][n][0], c2, -8.f);
                        float t1 = fmaf(sc[mi][n][1], c2, -8.f);
                        float t2 = fmaf(sc[mi][n][2], c2, -8.f);
                        float t3 = fmaf(sc[mi][n][3], c2, -8.f);
                        if (need_mask) {
                            const int cg = ct + nj * 16 + n * 8 + (lane & 3) * 2;
                            if (cg     > rg0)     t0 = -1e30f;
                            if (cg + 1 > rg0)     t1 = -1e30f;
                            if (cg     > rg0 + 8) t2 = -1e30f;
                            if (cg + 1 > rg0 + 8) t3 = -1e30f;
                        }
                        __half2 h01 = __floats2half2_rn(t0, t1);
                        __half2 h23 = __floats2half2_rn(t2, t3);
                        pf[mi][n * 2 + 0] = ex2h2(*(uint32_t*)&h01);
                        pf[mi][n * 2 + 1] = ex2h2(*(uint32_t*)&h23);
                    }
                }

                #pragma unroll
                for (int dj = 0; dj < 4; dj++) {
                    uint32_t vf[4];
                    const int row = nj * 16 + (lane & 7) + (((lane >> 3) & 1) << 3);
                    const int col = dj * 16 + (lane >> 4) * 8;
                    ldm_x4_t(vf, sptr(&vs[row * ASTR + col]));
                    #pragma unroll
                    for (int mi = 0; mi < 2; mi++) {
                        mma16816(out[mi][2 * dj],     pf[mi], &vf[0]);
                        mma16816(out[mi][2 * dj + 1], pf[mi], &vf[2]);
                    }
                }
                #pragma unroll
                for (int mi = 0; mi < 2; mi++)
                    mma16816(rs[mi], pf[mi], onesb);
            }
        }
    }

    if (half < 0) {
        #pragma unroll
        for (int mi = 0; mi < 2; mi++) {
            const float inv0 = 1.f / rs[mi][0];
            const float inv1 = 1.f / rs[mi][2];
            const int s0 = qt * 128 + wid * 32 + mi * 16 + (lane >> 2);
            const int s1 = s0 + 8;
            #pragma unroll
            for (int n = 0; n < 8; n++) {
                const int d = n * 8 + (lane & 3) * 2;
                __half2 v0 = __floats2half2_rn(out[mi][n][0] * inv0,
                                               out[mi][n][1] * inv0);
                __half2 v1 = __floats2half2_rn(out[mi][n][2] * inv1,
                                               out[mi][n][3] * inv1);
                *(__half2*)&O[((size_t)(b * CS + s0) * CE) + h * 64 + d] = v0;
                *(__half2*)&O[((size_t)(b * CS + s1) * CE) + h * 64 + d] = v1;
            }
        }
    } else {
        float* po = &g_po[half][0] +
                    ((size_t)((qt - 8) * 32 + bh) * 128) * 64;
        float* prs = &g_prs[half][0] + ((qt - 8) * 32 + bh) * 128;
        #pragma unroll
        for (int mi = 0; mi < 2; mi++) {
            const int r0 = wid * 32 + mi * 16 + (lane >> 2);
            const int r1 = r0 + 8;
            #pragma unroll
            for (int n = 0; n < 8; n++) {
                const int d = n * 8 + (lane & 3) * 2;
                *(float2*)&po[r0 * 64 + d] =
                    make_float2(out[mi][n][0], out[mi][n][1]);
                *(float2*)&po[r1 * 64 + d] =
                    make_float2(out[mi][n][2], out[mi][n][3]);
            }
            if ((lane & 3) == 0) {
                prs[r0] = rs[mi][0];
                prs[r1] = rs[mi][2];
            }
        }
    }
}

// ---------------------------------------------------------------------------
// Combine split-K partials for one 4-head group: O = (pA+pB)/(rsA+rsB).
// Elements: 8qt * 2b * 4h * 128r * 64d = 524288; 2 per thread -> 1024 blocks.
// ---------------------------------------------------------------------------
__global__ void __launch_bounds__(256) attn_combine(__half* __restrict__ O,
                                                    int h_base) {
    const int t = blockIdx.x * 256 + threadIdx.x;
    const int gi2 = t * 2;
    const int d = gi2 & 63;
    int rest = gi2 >> 6;
    const int r = rest & 127; rest >>= 7;
    const int hq = rest & 3;  rest >>= 2;
    const int b = rest & 1;
    const int qts = rest >> 1;
    const int bh = b * 16 + h_base + hq;
    const int row = (qts * 32 + bh) * 128 + r;
    const float2 a  = *(const float2*)&g_po[0][(size_t)row * 64 + d];
    const float2 b2 = *(const float2*)&g_po[1][(size_t)row * 64 + d];
    const float inv = 1.f / (g_prs[0][row] + g_prs[1][row]);
    const int s = (8 + qts) * 128 + r;
    __half2 o = __floats2half2_rn((a.x + b2.x) * inv, (a.y + b2.y) * inv);
    *(__half2*)&O[((size_t)(b * CS + s) * CE) + (h_base + hq) * 64 + d] = o;
}

// ---------------------------------------------------------------------------
// Launcher: head-quarter pipelines on 2 streams + chained K-quarter output
// projection on a third.
//   s0: cvtx_lo -> Q0(qkv,attn,comb) -> Q1(...)            -> [chain,C3] outQ3
//   s1: cvt_w -> cvtx_hi -> Q2(...) -> Q3(...)
//   s2: [W,C0] outQ0 -> [C2] outQ2 -> [C1] outQ1
// ---------------------------------------------------------------------------
extern "C" void kernel_launch(void* const* d_in, const int* in_sizes, int n_in,
                              void* d_out, int out_size)
{
    (void)in_sizes; (void)n_in; (void)out_size;
    const float* q   = (const float*)d_in[0];
    const float* k   = (const float*)d_in[1];
    const float* v   = (const float*)d_in[2];
    const float* w_q = (const float*)d_in[4];
    const float* b_q = (const float*)d_in[5];
    const float* w_k = (const float*)d_in[6];
    const float* b_k = (const float*)d_in[7];
    const float* w_v = (const float*)d_in[8];
    const float* b_v = (const float*)d_in[9];
    const float* w_o = (const float*)d_in[10];
    const float* b_o = (const float*)d_in[11];
    float* out = (float*)d_out;

    __half *pq, *pk, *pv, *patt, *paq, *pak, *pav, *pwq, *pwk, *pwv, *pwo;
    cudaGetSymbolAddress((void**)&pq, g_q);
    cudaGetSymbolAddress((void**)&pk, g_k);
    cudaGetSymbolAddress((void**)&pv, g_v);
    cudaGetSymbolAddress((void**)&patt, g_att);
    cudaGetSymbolAddress((void**)&paq, g_aq);
    cudaGetSymbolAddress((void**)&pak, g_ak);
    cudaGetSymbolAddress((void**)&pav, g_av);
    cudaGetSymbolAddress((void**)&pwq, g_wq);
    cudaGetSymbolAddress((void**)&pwk, g_wk);
    cudaGetSymbolAddress((void**)&pwv, g_wv);
    cudaGetSymbolAddress((void**)&pwo, g_wo);

    static cudaStream_t s1 = nullptr, s2 = nullptr;
    static cudaEvent_t evStart, evW, evX0, evX1;
    static cudaEvent_t evC[4], evChain;
    if (s1 == nullptr) {
        cudaStreamCreateWithFlags(&s1, cudaStreamNonBlocking);
        cudaStreamCreateWithFlags(&s2, cudaStreamNonBlocking);
        cudaEventCreateWithFlags(&evStart, cudaEventDisableTiming);
        cudaEventCreateWithFlags(&evW, cudaEventDisableTiming);
        cudaEventCreateWithFlags(&evX0, cudaEventDisableTiming);
        cudaEventCreateWithFlags(&evX1, cudaEventDisableTiming);
        for (int i = 0; i < 4; i++)
            cudaEventCreateWithFlags(&evC[i], cudaEventDisableTiming);
        cudaEventCreateWithFlags(&evChain, cudaEventDisableTiming);
    }

    cudaFuncSetAttribute(qkv_gemm,
                         cudaFuncAttributeMaxDynamicSharedMemorySize, GEMM_SMEM);
    cudaFuncSetAttribute(out_gemm_q0,
                         cudaFuncAttributeMaxDynamicSharedMemorySize, GEMM_SMEM);
    cudaFuncSetAttribute(out_gemm_qacc,
                         cudaFuncAttributeMaxDynamicSharedMemorySize, GEMM_SMEM);
    const int attn_smem = (128 * ASTR + 4 * 64 * ASTR) * (int)sizeof(__half);
    cudaFuncSetAttribute(attn_tc,
                         cudaFuncAttributeMaxDynamicSharedMemorySize, attn_smem);

    // Fork s1, s2 from the capture stream
    cudaEventRecord(evStart, 0);
    cudaStreamWaitEvent(s1, evStart, 0);
    cudaStreamWaitEvent(s2, evStart, 0);

    const int nw8 = CE * CE / 8;
    const int nx8h = CM * CE / 16;           // half the activation rows

    // s1: weight conversions, then activation upper half
    {
        CvtArgs wa;
        wa.in[0] = w_q; wa.in[1] = w_k; wa.in[2] = w_v; wa.in[3] = w_o;
        wa.out[0] = pwq; wa.out[1] = pwk; wa.out[2] = pwv; wa.out[3] = pwo;
        cvt_multi<<<dim3((nw8 + 255) / 256, 4), 256, 0, s1>>>(wa, nw8);
        cudaEventRecord(evW, s1);

        const size_t off = (size_t)(CM / 2) * CE;
        CvtArgs xh;
        xh.in[0] = q + off; xh.in[1] = k + off; xh.in[2] = v + off;
        xh.in[3] = q + off;
        xh.out[0] = paq + off; xh.out[1] = pak + off; xh.out[2] = pav + off;
        xh.out[3] = paq + off;
        cvt_multi<<<dim3((nx8h + 255) / 256, 3), 256, 0, s1>>>(xh, nx8h);
        cudaEventRecord(evX1, s1);
    }

    // s0: activation lower half
    {
        CvtArgs xl;
        xl.in[0] = q; xl.in[1] = k; xl.in[2] = v; xl.in[3] = q;
        xl.out[0] = paq; xl.out[1] = pak; xl.out[2] = pav; xl.out[3] = paq;
        cvt_multi<<<dim3((nx8h + 255) / 256, 3), 256>>>(xl, nx8h);
        cudaEventRecord(evX0, 0);
    }

    QKVArgs ga;
    ga.A[0] = paq; ga.A[1] = pak; ga.A[2] = pav;
    ga.W[0] = pwq; ga.W[1] = pwk; ga.W[2] = pwv;
    ga.bias[0] = b_q; ga.bias[1] = b_k; ga.bias[2] = b_v;
    ga.C[0] = pq; ga.C[1] = pk; ga.C[2] = pv;

    // Cross dependencies: s0 needs W and X1; s1 needs X0.
    cudaStreamWaitEvent(0, evW, 0);
    cudaStreamWaitEvent(0, evX1, 0);
    cudaStreamWaitEvent(s1, evX0, 0);

    // s0: quarters 0 and 1 (heads 0-3, 4-7)
    for (int iq = 0; iq < 2; iq++) {
        QKVArgs g = ga; g.n_base = 2 * iq;
        qkv_gemm<<<dim3(2, CM / 128, 3), 256, GEMM_SMEM>>>(g);
        attn_tc<<<dim3(24, 8), 128, attn_smem>>>(pq, pk, pv, patt, 4 * iq);
        attn_combine<<<1024, 256>>>(patt, 4 * iq);
        cudaEventRecord(evC[iq], 0);
    }

    // s1: quarters 2 and 3 (heads 8-11, 12-15)
    for (int iq = 2; iq < 4; iq++) {
        QKVArgs g = ga; g.n_base = 2 * iq;
        qkv_gemm<<<dim3(2, CM / 128, 3), 256, GEMM_SMEM, s1>>>(g);
        attn_tc<<<dim3(24, 8), 128, attn_smem, s1>>>(pq, pk, pv, patt, 4 * iq);
        attn_combine<<<1024, 256, 0, s1>>>(patt, 4 * iq);
        cudaEventRecord(evC[iq], s1);
    }

    // s2: chained output projection quarters (RMW serialized)
    cudaStreamWaitEvent(s2, evW, 0);
    cudaStreamWaitEvent(s2, evC[0], 0);
    out_gemm_q0<<<dim3(CE / 128, CM / 128), 256, GEMM_SMEM, s2>>>(
        patt, pwo, b_o, out);
    cudaStreamWaitEvent(s2, evC[2], 0);
    out_gemm_qacc<<<dim3(CE / 128, CM / 128), 256, GEMM_SMEM, s2>>>(
        patt + 2 * (CE / 4), pwo + 2 * (CE / 4), out);
    cudaStreamWaitEvent(s2, evC[1], 0);
    out_gemm_qacc<<<dim3(CE / 128, CM / 128), 256, GEMM_SMEM, s2>>>(
        patt + 1 * (CE / 4), pwo + 1 * (CE / 4), out);
    cudaEventRecord(evChain, s2);

    // Final quarter on the capture stream
    cudaStreamWaitEvent(0, evChain, 0);
    cudaStreamWaitEvent(0, evC[3], 0);
    out_gemm_qacc<<<dim3(CE / 128, CM / 128), 256, GEMM_SMEM>>>(
        patt + 3 * (CE / 4), pwo + 3 * (CE / 4), out);
}